// round 14
// baseline (speedup 1.0000x reference)
#include <cuda_runtime.h>
#include <cstdint>

// Problem constants (dataset-fixed: IN=(32,3,512,512), OUT=256, scale=0.5)
#define BC      96
#define IN_HW   512
#define OUT_HW  256
#define TOH     8             // oh rows per block (two 4-row halves)
#define RPH     4             // rows per half (even!)
#define MAX_T   12
#define HALFP   260           // odd-column region offset, in 8-byte units
#define MIDW    520           // mid2 row length in 8-byte units

typedef unsigned long long ull;

__device__ __forceinline__ ull pack2(float x, float y) {
    ull r; asm("mov.b64 %0, {%1, %2};" : "=l"(r) : "f"(x), "f"(y)); return r;
}
__device__ __forceinline__ void unpack2(ull v, float& x, float& y) {
    asm("mov.b64 {%0, %1}, %2;" : "=f"(x), "=f"(y) : "l"(v));
}
__device__ __forceinline__ void ffma2(ull& a, ull w, ull v) {
    asm("fma.rn.f32x2 %0, %1, %2, %0;" : "+l"(a) : "l"(w), "l"(v));
}
__device__ __forceinline__ ull fadd2(ull a, ull b) {
    ull r; asm("add.rn.f32x2 %0, %1, %2;" : "=l"(r) : "l"(a), "l"(b)); return r;
}

// even/odd split position (8-byte units): fixed-tap gathers become stride-1.
__device__ __forceinline__ int pos_of(int w) { return (w >> 1) + (w & 1) * HALFP; }

// Dynamic smem layout (bytes), TOH = 8:
//   [0, 16640)        mid2 : ull[TOH/2][MIDW]              (4*520*8)
//   [16640, 17408)    hw2  : ull[MAX_T][TOH]
//   [17408, 17792)    hf_s : int[MAX_T][TOH]
//   [17792, 17808)    mbar : 8B mbarrier (+pad to 16)
//   [17808, ...)      in_s : float[NROWS][512]  (bulk-copied input slab)
#define OFF_HW2  16640
#define OFF_HF   17408
#define OFF_MBAR 17792
#define OFF_IN   17808

// ---------------------------------------------------------------------------
// Fused bicubic downsample: ONE cp.async.bulk stages the contiguous input
// slab (rows lo..lo+NROWS of the plane) -> zero per-thread staging work.
// Block = 512 threads = one plane x 8 oh x full W, two 4-row halves.
//   1) Phase 1 (H): circular register window over the smem slab (each byte
//      crosses the LDS crossbar once), broadcast-LDS weights, FFMA2.
//   2) Phase 2 (W): conflict-free LDS.64 gathers on packed row pairs.
// Edge tiles (mirror folds) use a global-read generic path.
// ---------------------------------------------------------------------------
template<int TAPS>
__global__ __launch_bounds__(512) void resize_fused(
    const ull*   __restrict__ in,     // (BC, IN_HW, 256) column pairs
    const float* __restrict__ wh, const int* __restrict__ fh,   // H tables
    const float* __restrict__ ww, const int* __restrict__ fw,   // W tables
    float*       __restrict__ out)    // (BC, OUT_HW, OUT_HW)
{
    constexpr int NROWS = 2 * TOH - 2 + TAPS;         // input rows per slab
    constexpr unsigned SLAB = NROWS * IN_HW * 4;      // slab bytes

    extern __shared__ char smem[];
    ull*   mid2 = (ull*)smem;                 // [TOH/2][MIDW]
    ull*   hw2  = (ull*)(smem + OFF_HW2);     // [TAPS][TOH]
    int*   hf_s = (int*)(smem + OFF_HF);      // [TAPS][TOH]
    float* in_s = (float*)(smem + OFF_IN);    // [NROWS][512]
    const ull* ins = (const ull*)in_s;        // [NROWS][256]

    const unsigned mbar = (unsigned)__cvta_generic_to_shared(smem + OFF_MBAR);
    const unsigned sdst = (unsigned)__cvta_generic_to_shared(smem + OFF_IN);

    const int tid   = threadIdx.x;            // 0..511
    const int col   = tid & 255;              // owns input cols (2c, 2c+1)
    const int r0    = (tid >> 8) * RPH;       // first oh row of this half
    const int oh0   = blockIdx.x * TOH;
    const int plane = blockIdx.y;

    // ---- 0) Single-thread bulk async copy of the whole slab ----
    const int b0raw = fh[oh0];                        // uniform LDG broadcast
    int lo = b0raw < 0 ? 0 : b0raw;
    if (lo > IN_HW - NROWS) lo = IN_HW - NROWS;

    if (tid == 0) {
        asm volatile("mbarrier.init.shared.b64 [%0], %1;"
                     :: "r"(mbar), "r"(1u) : "memory");
        asm volatile("fence.proxy.async.shared::cta;" ::: "memory");
        asm volatile("mbarrier.arrive.expect_tx.shared.b64 _, [%0], %1;"
                     :: "r"(mbar), "r"(SLAB) : "memory");
        const char* gsrc = (const char*)in
                         + ((size_t)plane * IN_HW * IN_HW
                          + (size_t)lo * IN_HW) * sizeof(float);
        asm volatile(
            "cp.async.bulk.shared::cta.global.mbarrier::complete_tx::bytes "
            "[%0], [%1], %2, [%3];"
            :: "r"(sdst), "l"(gsrc), "r"(SLAB), "r"(mbar) : "memory");
    }

    // ---- Table loads overlap the bulk copy ----
    if (tid < TAPS * TOH) {
        const int t = tid / TOH, r = tid % TOH;
        const float w = wh[t * OUT_HW + oh0 + r];
        hw2 [t * TOH + r] = pack2(w, w);
        hf_s[t * TOH + r] = fh[t * OUT_HW + oh0 + r];
    }
    __syncthreads();                          // mbarrier init + tables visible

    // Fast iff H fov is linear: base + 2r + t (interior tiles => lo == b0raw).
    bool okp = true;
    if (tid < TAPS * TOH) {
        const int t = tid / TOH, r = tid % TOH;
        okp = (hf_s[t * TOH + r] == b0raw + 2 * r + t);
    }
    const int fast = __syncthreads_and(okp);

    // Wait for the slab (acquire orders subsequent LDS reads).
    {
        unsigned done;
        asm volatile(
            "{\n\t.reg .pred p;\n\t"
            "mbarrier.try_wait.parity.acquire.cta.shared::cta.b64 p, [%1], 0;\n\t"
            "selp.b32 %0, 1, 0, p;\n\t}"
            : "=r"(done) : "r"(mbar) : "memory");
        if (!done) {
            asm volatile(
                "{\n\t.reg .pred P1;\n\t"
                "WL_%=:\n\t"
                "mbarrier.try_wait.parity.acquire.cta.shared::cta.b64 P1, [%0], 0, 0x989680;\n\t"
                "@P1 bra.uni WD_%=;\n\t"
                "bra.uni WL_%=;\n\t"
                "WD_%=:\n\t}"
                :: "r"(mbar) : "memory");
        }
    }

    const ull* base = in + (size_t)plane * IN_HW * 256 + col;

    if (fast) {
        // ---- Phase 1 fast: circular register window over the smem slab ----
        // fast => lo == b0raw; slab row for (r, t) = 2r + t.
        const ull* sb = ins + col;
        ull v[TAPS];
        #pragma unroll
        for (int t = 0; t < TAPS; ++t)
            v[t] = sb[(size_t)(2 * r0 + t) * 256];

        ull stash = 0;
        #pragma unroll
        for (int j = 0; j < RPH; ++j) {
            const int r = r0 + j;
            ull a0 = 0, a1 = 0;
            ffma2(a0, hw2[0 * TOH + r], v[(2 * j)     % TAPS]);
            ffma2(a1, hw2[1 * TOH + r], v[(2 * j + 1) % TAPS]);
            if (j < RPH - 1) {                // refill the two consumed slots
                v[(2 * j)     % TAPS] = sb[(size_t)(2 * r0 + 2 * j + TAPS)     * 256];
                v[(2 * j + 1) % TAPS] = sb[(size_t)(2 * r0 + 2 * j + TAPS + 1) * 256];
            }
            #pragma unroll
            for (int t = 2; t < TAPS; ++t) {
                if (t & 1) ffma2(a1, hw2[t * TOH + r], v[(2 * j + t) % TAPS]);
                else       ffma2(a0, hw2[t * TOH + r], v[(2 * j + t) % TAPS]);
            }
            const ull acc = fadd2(a0, a1);    // (evenColVal, oddColVal)
            if ((j & 1) == 0) stash = acc;
            else {                            // repack across the row pair
                float ex, ey, ox, oy;
                unpack2(stash, ex, ey);
                unpack2(acc,   ox, oy);
                const int rp = (r0 >> 1) + (j >> 1);
                mid2[rp * MIDW + col]         = pack2(ex, ox);
                mid2[rp * MIDW + col + HALFP] = pack2(ey, oy);
            }
        }
    } else {
        // ---- Phase 1 generic (edge tiles with mirror folds): global reads ----
        float sx = 0.f, sy = 0.f;
        #pragma unroll
        for (int j = 0; j < RPH; ++j) {
            const int r = r0 + j;
            float ax = 0.f, ay = 0.f;
            #pragma unroll
            for (int t = 0; t < TAPS; ++t) {
                float w, wd; unpack2(hw2[t * TOH + r], w, wd);
                float x, y;  unpack2(base[(size_t)hf_s[t * TOH + r] * 256], x, y);
                ax = fmaf(w, x, ax);
                ay = fmaf(w, y, ay);
            }
            if ((j & 1) == 0) { sx = ax; sy = ay; }
            else {
                const int rp = (r0 >> 1) + (j >> 1);
                mid2[rp * MIDW + col]         = pack2(sx, ax);
                mid2[rp * MIDW + col + HALFP] = pack2(sy, ay);
            }
        }
    }

    // Phase-2 per-thread tables AFTER phase 1 (short live range, no spills).
    ull pw[TAPS];
    int pr[TAPS];
    #pragma unroll
    for (int t = 0; t < TAPS; ++t) {
        const float w = ww[t * OUT_HW + col];
        pw[t] = pack2(w, w);
        pr[t] = pos_of(fw[t * OUT_HW + col]);
    }
    __syncthreads();

    // ---- Phase 2: W resize on packed row pairs ----
    float* ob = out + ((size_t)plane * OUT_HW + oh0 + r0) * OUT_HW + col;
    #pragma unroll
    for (int p = 0; p < RPH / 2; ++p) {
        const int rp = (r0 >> 1) + p;
        ull a0 = 0, a1 = 0;
        #pragma unroll
        for (int t = 0; t < TAPS; ++t) {
            if (t & 1) ffma2(a1, pw[t], mid2[rp * MIDW + pr[t]]);
            else       ffma2(a0, pw[t], mid2[rp * MIDW + pr[t]]);
        }
        float x, y; unpack2(fadd2(a0, a1), x, y);
        ob[(size_t)(2 * p)     * OUT_HW] = x;   // row r0+2p
        ob[(size_t)(2 * p + 1) * OUT_HW] = y;   // row r0+2p+1
    }
}

// ---------------------------------------------------------------------------
// Generic-taps fallback (any taps; table path everywhere; static smem).
// ---------------------------------------------------------------------------
__global__ __launch_bounds__(512) void resize_fused_generic(
    const ull*   __restrict__ in,
    const float* __restrict__ wh, const int* __restrict__ fh,
    const float* __restrict__ ww, const int* __restrict__ fw,
    float*       __restrict__ out, int taps)
{
    __shared__ ull   mid2[TOH / 2][MIDW];
    __shared__ float hw_s[MAX_T][TOH];
    __shared__ int   hf_s[MAX_T][TOH];

    const int tid   = threadIdx.x;
    const int col   = tid & 255;
    const int r0    = (tid >> 8) * RPH;
    const int oh0   = blockIdx.x * TOH;
    const int plane = blockIdx.y;

    if (tid < taps * TOH) {
        const int t = tid / TOH, r = tid % TOH;
        hw_s[t][r] = wh[t * OUT_HW + oh0 + r];
        hf_s[t][r] = fh[t * OUT_HW + oh0 + r];
    }
    float wr[MAX_T]; int pr[MAX_T];
    #pragma unroll
    for (int t = 0; t < MAX_T; ++t) {
        if (t < taps) {
            wr[t] = ww[t * OUT_HW + col];
            pr[t] = pos_of(fw[t * OUT_HW + col]);
        } else { wr[t] = 0.f; pr[t] = 0; }
    }
    __syncthreads();

    const ull* base = in + (size_t)plane * IN_HW * 256 + col;
    float sx = 0.f, sy = 0.f;
    for (int j = 0; j < RPH; ++j) {
        const int r = r0 + j;
        float ax = 0.f, ay = 0.f;
        #pragma unroll
        for (int t = 0; t < MAX_T; ++t) {
            if (t < taps) {
                float x, y; unpack2(base[(size_t)hf_s[t][r] * 256], x, y);
                ax = fmaf(hw_s[t][r], x, ax);
                ay = fmaf(hw_s[t][r], y, ay);
            }
        }
        if ((j & 1) == 0) { sx = ax; sy = ay; }
        else {
            const int rp = (r0 >> 1) + (j >> 1);
            mid2[rp][col]         = pack2(sx, ax);
            mid2[rp][col + HALFP] = pack2(sy, ay);
        }
    }
    __syncthreads();

    float* ob = out + ((size_t)plane * OUT_HW + oh0 + r0) * OUT_HW + col;
    for (int p = 0; p < RPH / 2; ++p) {
        const int rp = (r0 >> 1) + p;
        float ax = 0.f, ay = 0.f;
        #pragma unroll
        for (int t = 0; t < MAX_T; ++t) {
            if (t < taps) {
                float x, y; unpack2(mid2[rp][pr[t]], x, y);
                ax = fmaf(wr[t], x, ax);
                ay = fmaf(wr[t], y, ay);
            }
        }
        ob[(size_t)(2 * p)     * OUT_HW] = ax;
        ob[(size_t)(2 * p + 1) * OUT_HW] = ay;
    }
}

// ---------------------------------------------------------------------------
// Inputs (metadata order): in_tensor, w2, fov2 (H axis), w3, fov3 (W axis)
// ---------------------------------------------------------------------------
#define LAUNCH_T(T)                                                            \
    do {                                                                       \
        constexpr int nrows = 2 * TOH - 2 + (T);                               \
        const int smemB = OFF_IN + nrows * IN_HW * 4;                          \
        cudaFuncSetAttribute(resize_fused<(T)>,                                \
            cudaFuncAttributeMaxDynamicSharedMemorySize, smemB);               \
        resize_fused<(T)><<<grid, 512, smemB>>>(in, w2, fov2, w3, fov3, out);  \
    } while (0)

extern "C" void kernel_launch(void* const* d_in, const int* in_sizes, int n_in,
                              void* d_out, int out_size)
{
    const ull*   in   = (const ull*)  d_in[0];
    const float* w2   = (const float*)d_in[1];
    const int*   fov2 = (const int*)  d_in[2];
    const float* w3   = (const float*)d_in[3];
    const int*   fov3 = (const int*)  d_in[4];
    float* out = (float*)d_out;

    const int taps = in_sizes[1] / OUT_HW;
    dim3 grid(OUT_HW / TOH, BC);                  // (32, 96) = 3072 blocks

    switch (taps) {
    case 6:  LAUNCH_T(6);  break;
    case 7:  LAUNCH_T(7);  break;
    case 8:  LAUNCH_T(8);  break;
    case 9:  LAUNCH_T(9);  break;
    case 10: LAUNCH_T(10); break;
    case 11: LAUNCH_T(11); break;
    case 12: LAUNCH_T(12); break;
    default: resize_fused_generic<<<grid, 512>>>(in, w2, fov2, w3, fov3, out, taps); break;
    }
}

// round 16
// speedup vs baseline: 1.3506x; 1.3506x over previous
#include <cuda_runtime.h>
#include <cstdint>

// Problem constants (dataset-fixed: IN=(32,3,512,512), OUT=256, scale=0.5)
#define BC      96
#define IN_HW   512
#define OUT_HW  256
#define TOH     8             // oh rows per sub-tile (two 4-row halves)
#define BTOH    16            // oh rows per block (2 sub-tiles, double-buffered)
#define RPH     4             // rows per half
#define MAX_T   12
#define HALFP   260           // odd-column region offset, in 8-byte units
#define MIDW    520           // mid2 row length in 8-byte units

typedef unsigned long long ull;

__device__ __forceinline__ ull pack2(float x, float y) {
    ull r; asm("mov.b64 %0, {%1, %2};" : "=l"(r) : "f"(x), "f"(y)); return r;
}
__device__ __forceinline__ void unpack2(ull v, float& x, float& y) {
    asm("mov.b64 {%0, %1}, %2;" : "=f"(x), "=f"(y) : "l"(v));
}
__device__ __forceinline__ void ffma2(ull& a, ull w, ull v) {
    asm("fma.rn.f32x2 %0, %1, %2, %0;" : "+l"(a) : "l"(w), "l"(v));
}
__device__ __forceinline__ ull fadd2(ull a, ull b) {
    ull r; asm("add.rn.f32x2 %0, %1, %2;" : "=l"(r) : "l"(a), "l"(b)); return r;
}
__device__ __forceinline__ void cp_async16(void* smem_dst, const void* gmem_src) {
    unsigned s = (unsigned)__cvta_generic_to_shared(smem_dst);
    asm volatile("cp.async.cg.shared.global [%0], [%1], 16;" :: "r"(s), "l"(gmem_src));
}
#define CP_COMMIT() asm volatile("cp.async.commit_group;" ::: "memory")
#define CP_WAIT(N)  asm volatile("cp.async.wait_group %0;" :: "n"(N) : "memory")

// even/odd split position (8-byte units): fixed-tap gathers become stride-1.
__device__ __forceinline__ int pos_of(int w) { return (w >> 1) + (w & 1) * HALFP; }

// Dynamic smem layout (bytes):
//   [0, 16640)        mid2 : ull[TOH/2][MIDW]     (reused by both sub-tiles)
//   [16640, 18176)    hw2  : ull[MAX_T][BTOH]     (packed (w,w) H weights)
//   [18176, 18944)    hf_s : int[MAX_T][BTOH]
//   [18944, ...)      slab0, slab1 : float[NROWS][512] each
#define OFF_HW2  16640
#define OFF_HF   18176
#define OFF_S0   18944

// ---------------------------------------------------------------------------
// Sub-tile worker: phase 1 (H, circular register window over slab or generic
// global reads) into mid2, then phase 2 (W, conflict-free LDS.64) to out.
// Caller provides barriers around mid2 reuse.
// ---------------------------------------------------------------------------
template<int TAPS>
__device__ __forceinline__ void do_tile(
    const ull* __restrict__ ins,      // staged slab ([NROWS][256]) for this tile
    const ull* __restrict__ hw2, const int* __restrict__ hf_s, int rbase,
    ull* __restrict__ mid2,
    const ull* __restrict__ gbase,    // global plane base + col (generic path)
    const float* __restrict__ ww, const int* __restrict__ fw,
    float* __restrict__ ob,           // out + ((plane*256+oh0+rbase+r0)*256)+col
    int fast, int col, int r0)
{
    if (fast) {
        const ull* sb = ins + col;
        ull v[TAPS];
        #pragma unroll
        for (int t = 0; t < TAPS; ++t)
            v[t] = sb[(size_t)(2 * r0 + t) * 256];

        ull stash = 0;
        #pragma unroll
        for (int j = 0; j < RPH; ++j) {
            const int r = rbase + r0 + j;
            ull a0 = 0, a1 = 0;
            ffma2(a0, hw2[0 * BTOH + r], v[(2 * j)     % TAPS]);
            ffma2(a1, hw2[1 * BTOH + r], v[(2 * j + 1) % TAPS]);
            if (j < RPH - 1) {                // refill the two consumed slots
                v[(2 * j)     % TAPS] = sb[(size_t)(2 * r0 + 2 * j + TAPS)     * 256];
                v[(2 * j + 1) % TAPS] = sb[(size_t)(2 * r0 + 2 * j + TAPS + 1) * 256];
            }
            #pragma unroll
            for (int t = 2; t < TAPS; ++t) {
                if (t & 1) ffma2(a1, hw2[t * BTOH + r], v[(2 * j + t) % TAPS]);
                else       ffma2(a0, hw2[t * BTOH + r], v[(2 * j + t) % TAPS]);
            }
            const ull acc = fadd2(a0, a1);    // (evenColVal, oddColVal)
            if ((j & 1) == 0) stash = acc;
            else {                            // repack across the row pair
                float ex, ey, ox, oy;
                unpack2(stash, ex, ey);
                unpack2(acc,   ox, oy);
                const int rp = (r0 >> 1) + (j >> 1);
                mid2[rp * MIDW + col]         = pack2(ex, ox);
                mid2[rp * MIDW + col + HALFP] = pack2(ey, oy);
            }
        }
    } else {
        // generic (edge tiles with mirror folds): table-driven global reads
        float sx = 0.f, sy = 0.f;
        #pragma unroll
        for (int j = 0; j < RPH; ++j) {
            const int r = rbase + r0 + j;
            float ax = 0.f, ay = 0.f;
            #pragma unroll
            for (int t = 0; t < TAPS; ++t) {
                float w, wd; unpack2(hw2[t * BTOH + r], w, wd);
                float x, y;  unpack2(gbase[(size_t)hf_s[t * BTOH + r] * 256], x, y);
                ax = fmaf(w, x, ax);
                ay = fmaf(w, y, ay);
            }
            if ((j & 1) == 0) { sx = ax; sy = ay; }
            else {
                const int rp = (r0 >> 1) + (j >> 1);
                mid2[rp * MIDW + col]         = pack2(sx, ax);
                mid2[rp * MIDW + col + HALFP] = pack2(sy, ay);
            }
        }
    }

    // Phase-2 per-thread tables (short live range; 2nd call hits L1).
    ull pw[TAPS];
    int pr[TAPS];
    #pragma unroll
    for (int t = 0; t < TAPS; ++t) {
        const float w = ww[t * OUT_HW + col];
        pw[t] = pack2(w, w);
        pr[t] = pos_of(fw[t * OUT_HW + col]);
    }
    __syncthreads();                          // mid2 fully written

    #pragma unroll
    for (int p = 0; p < RPH / 2; ++p) {
        const int rp = (r0 >> 1) + p;
        ull a0 = 0, a1 = 0;
        #pragma unroll
        for (int t = 0; t < TAPS; ++t) {
            if (t & 1) ffma2(a1, pw[t], mid2[rp * MIDW + pr[t]]);
            else       ffma2(a0, pw[t], mid2[rp * MIDW + pr[t]]);
        }
        float x, y; unpack2(fadd2(a0, a1), x, y);
        ob[(size_t)(2 * p)     * OUT_HW] = x;
        ob[(size_t)(2 * p + 1) * OUT_HW] = y;
    }
}

// ---------------------------------------------------------------------------
// Double-buffered fused bicubic downsample. Block = 512 threads = one plane
// x 16 oh (two TOH=8 sub-tiles with separate cp.async slabs). Slab1's fetch
// overlaps sub-tile0's compute -> DRAM duty cycle rises.
// ---------------------------------------------------------------------------
template<int TAPS>
__global__ __launch_bounds__(512) void resize_fused(
    const ull*   __restrict__ in,     // (BC, IN_HW, 256) column pairs
    const float* __restrict__ wh, const int* __restrict__ fh,   // H tables
    const float* __restrict__ ww, const int* __restrict__ fw,   // W tables
    float*       __restrict__ out)    // (BC, OUT_HW, OUT_HW)
{
    constexpr int NROWS  = 2 * TOH - 2 + TAPS;        // input rows per slab
    constexpr int CHUNKS = NROWS * (IN_HW * 4 / 16);  // 16B chunks per slab
    constexpr int SLABB  = NROWS * IN_HW * 4;         // slab bytes

    extern __shared__ char smem[];
    ull*   mid2 = (ull*)smem;                 // [TOH/2][MIDW]
    ull*   hw2  = (ull*)(smem + OFF_HW2);     // [TAPS][BTOH]
    int*   hf_s = (int*)(smem + OFF_HF);      // [TAPS][BTOH]
    char*  s0   = smem + OFF_S0;              // slab0
    char*  s1   = smem + OFF_S0 + SLABB;      // slab1

    const int tid   = threadIdx.x;            // 0..511
    const int col   = tid & 255;              // owns input cols (2c, 2c+1)
    const int r0    = (tid >> 8) * RPH;       // first local oh row of this half
    const int oh0   = blockIdx.x * BTOH;
    const int plane = blockIdx.y;

    // ---- 0) Stage both slabs up front (two commit groups) ----
    const int b0 = fh[oh0];                   // uniform LDG broadcasts
    const int b1 = fh[oh0 + TOH];
    int lo0 = b0 < 0 ? 0 : b0; if (lo0 > IN_HW - NROWS) lo0 = IN_HW - NROWS;
    int lo1 = b1 < 0 ? 0 : b1; if (lo1 > IN_HW - NROWS) lo1 = IN_HW - NROWS;
    {
        const char* pbase = (const char*)in
                          + (size_t)plane * IN_HW * IN_HW * sizeof(float);
        const char* g0 = pbase + (size_t)lo0 * IN_HW * sizeof(float);
        const char* g1 = pbase + (size_t)lo1 * IN_HW * sizeof(float);
        #pragma unroll
        for (int k = 0; k < (CHUNKS + 511) / 512; ++k) {
            const int i = tid + k * 512;
            if (i < CHUNKS) cp_async16(s0 + (size_t)i * 16, g0 + (size_t)i * 16);
        }
        CP_COMMIT();
        #pragma unroll
        for (int k = 0; k < (CHUNKS + 511) / 512; ++k) {
            const int i = tid + k * 512;
            if (i < CHUNKS) cp_async16(s1 + (size_t)i * 16, g1 + (size_t)i * 16);
        }
        CP_COMMIT();
    }

    // ---- Table loads overlap the copies (16 oh rows of tables) ----
    if (tid < TAPS * BTOH) {
        const int t = tid / BTOH, r = tid % BTOH;
        const float w = wh[t * OUT_HW + oh0 + r];
        hw2 [t * BTOH + r] = pack2(w, w);
        hf_s[t * BTOH + r] = fh[t * OUT_HW + oh0 + r];
    }
    __syncthreads();

    // Fast iff BOTH sub-tiles' H fov is linear (base + 2r + t). Linearity
    // implies base in [0, IN_HW-NROWS] so lo == base automatically.
    bool okp = true;
    if (tid < TAPS * BTOH) {
        const int t = tid / BTOH, r = tid % BTOH;
        const int base = (r < TOH) ? b0 : b1;
        okp = (hf_s[t * BTOH + r] == base + 2 * (r & (TOH - 1)) + t);
    }
    const int fast = __syncthreads_and(okp);

    const ull* gbase = in + (size_t)plane * IN_HW * 256 + col;

    // ---- Sub-tile 0: wait for slab0 only (slab1 still streaming) ----
    CP_WAIT(1);
    __syncthreads();                          // all threads' slab0 chunks visible
    do_tile<TAPS>((const ull*)s0, hw2, hf_s, 0, mid2, gbase, ww, fw,
                  out + ((size_t)plane * OUT_HW + oh0 + r0) * OUT_HW + col,
                  fast, col, r0);

    // ---- Sub-tile 1: wait for slab1; barrier also protects mid2 reuse ----
    CP_WAIT(0);
    __syncthreads();
    do_tile<TAPS>((const ull*)s1, hw2, hf_s, TOH, mid2, gbase, ww, fw,
                  out + ((size_t)plane * OUT_HW + oh0 + TOH + r0) * OUT_HW + col,
                  fast, col, r0);
}

// ---------------------------------------------------------------------------
// Generic-taps fallback (any taps; table path everywhere; static smem).
// ---------------------------------------------------------------------------
__global__ __launch_bounds__(512) void resize_fused_generic(
    const ull*   __restrict__ in,
    const float* __restrict__ wh, const int* __restrict__ fh,
    const float* __restrict__ ww, const int* __restrict__ fw,
    float*       __restrict__ out, int taps)
{
    __shared__ ull   mid2[TOH / 2][MIDW];
    __shared__ float hw_s[MAX_T][TOH];
    __shared__ int   hf_s[MAX_T][TOH];

    const int tid   = threadIdx.x;
    const int col   = tid & 255;
    const int r0    = (tid >> 8) * RPH;
    const int oh0   = blockIdx.x * TOH;
    const int plane = blockIdx.y;

    if (tid < taps * TOH) {
        const int t = tid / TOH, r = tid % TOH;
        hw_s[t][r] = wh[t * OUT_HW + oh0 + r];
        hf_s[t][r] = fh[t * OUT_HW + oh0 + r];
    }
    float wr[MAX_T]; int pr[MAX_T];
    #pragma unroll
    for (int t = 0; t < MAX_T; ++t) {
        if (t < taps) {
            wr[t] = ww[t * OUT_HW + col];
            pr[t] = pos_of(fw[t * OUT_HW + col]);
        } else { wr[t] = 0.f; pr[t] = 0; }
    }
    __syncthreads();

    const ull* base = in + (size_t)plane * IN_HW * 256 + col;
    float sx = 0.f, sy = 0.f;
    for (int j = 0; j < RPH; ++j) {
        const int r = r0 + j;
        float ax = 0.f, ay = 0.f;
        #pragma unroll
        for (int t = 0; t < MAX_T; ++t) {
            if (t < taps) {
                float x, y; unpack2(base[(size_t)hf_s[t][r] * 256], x, y);
                ax = fmaf(hw_s[t][r], x, ax);
                ay = fmaf(hw_s[t][r], y, ay);
            }
        }
        if ((j & 1) == 0) { sx = ax; sy = ay; }
        else {
            const int rp = (r0 >> 1) + (j >> 1);
            mid2[rp][col]         = pack2(sx, ax);
            mid2[rp][col + HALFP] = pack2(sy, ay);
        }
    }
    __syncthreads();

    float* ob = out + ((size_t)plane * OUT_HW + oh0 + r0) * OUT_HW + col;
    for (int p = 0; p < RPH / 2; ++p) {
        const int rp = (r0 >> 1) + p;
        float ax = 0.f, ay = 0.f;
        #pragma unroll
        for (int t = 0; t < MAX_T; ++t) {
            if (t < taps) {
                float x, y; unpack2(mid2[rp][pr[t]], x, y);
                ax = fmaf(wr[t], x, ax);
                ay = fmaf(wr[t], y, ay);
            }
        }
        ob[(size_t)(2 * p)     * OUT_HW] = ax;
        ob[(size_t)(2 * p + 1) * OUT_HW] = ay;
    }
}

// ---------------------------------------------------------------------------
// Inputs (metadata order): in_tensor, w2, fov2 (H axis), w3, fov3 (W axis)
// ---------------------------------------------------------------------------
#define LAUNCH_T(T)                                                            \
    do {                                                                       \
        constexpr int nrows = 2 * TOH - 2 + (T);                               \
        const int smemB = OFF_S0 + 2 * nrows * IN_HW * 4;                      \
        cudaFuncSetAttribute(resize_fused<(T)>,                                \
            cudaFuncAttributeMaxDynamicSharedMemorySize, smemB);               \
        resize_fused<(T)><<<gridF, 512, smemB>>>(in, w2, fov2, w3, fov3, out); \
    } while (0)

extern "C" void kernel_launch(void* const* d_in, const int* in_sizes, int n_in,
                              void* d_out, int out_size)
{
    const ull*   in   = (const ull*)  d_in[0];
    const float* w2   = (const float*)d_in[1];
    const int*   fov2 = (const int*)  d_in[2];
    const float* w3   = (const float*)d_in[3];
    const int*   fov3 = (const int*)  d_in[4];
    float* out = (float*)d_out;

    const int taps = in_sizes[1] / OUT_HW;
    dim3 gridF(OUT_HW / BTOH, BC);                // (16, 96) = 1536 blocks
    dim3 gridG(OUT_HW / TOH,  BC);                // (32, 96) fallback

    switch (taps) {
    case 6:  LAUNCH_T(6);  break;
    case 7:  LAUNCH_T(7);  break;
    case 8:  LAUNCH_T(8);  break;
    case 9:  LAUNCH_T(9);  break;
    case 10: LAUNCH_T(10); break;
    case 11: LAUNCH_T(11); break;
    case 12: LAUNCH_T(12); break;
    default: resize_fused_generic<<<gridG, 512>>>(in, w2, fov2, w3, fov3, out, taps); break;
    }
}

// round 17
// speedup vs baseline: 1.4130x; 1.0462x over previous
#include <cuda_runtime.h>
#include <cstdint>

// Problem constants (dataset-fixed: IN=(32,3,512,512), OUT=256, scale=0.5)
#define BC      96
#define IN_HW   512
#define OUT_HW  256
#define TOH     4             // oh rows per block
#define RPH     4             // rows per thread (all threads, one pass)
#define THREADS 256
#define MAX_T   12
#define HALFP   260           // odd-column region offset, in 8-byte units
#define MIDW    520           // mid2 row length in 8-byte units

typedef unsigned long long ull;

__device__ __forceinline__ ull pack2(float x, float y) {
    ull r; asm("mov.b64 %0, {%1, %2};" : "=l"(r) : "f"(x), "f"(y)); return r;
}
__device__ __forceinline__ void unpack2(ull v, float& x, float& y) {
    asm("mov.b64 {%0, %1}, %2;" : "=f"(x), "=f"(y) : "l"(v));
}
__device__ __forceinline__ void ffma2(ull& a, ull w, ull v) {
    asm("fma.rn.f32x2 %0, %1, %2, %0;" : "+l"(a) : "l"(w), "l"(v));
}
__device__ __forceinline__ ull fadd2(ull a, ull b) {
    ull r; asm("add.rn.f32x2 %0, %1, %2;" : "=l"(r) : "l"(a), "l"(b)); return r;
}
__device__ __forceinline__ void cp_async16(void* smem_dst, const void* gmem_src) {
    unsigned s = (unsigned)__cvta_generic_to_shared(smem_dst);
    asm volatile("cp.async.cg.shared.global [%0], [%1], 16;" :: "r"(s), "l"(gmem_src));
}

// even/odd split position (8-byte units): fixed-tap gathers become stride-1.
__device__ __forceinline__ int pos_of(int w) { return (w >> 1) + (w & 1) * HALFP; }

// Dynamic smem layout (bytes), TOH = 4:
//   [0, 8320)        mid2 : ull[TOH/2][MIDW]               (2*520*8)
//   [8320, 8704)     hw2  : ull[MAX_T][TOH]
//   [8704, 8896)     hf_s : int[MAX_T][TOH]
//   [8960, ...)      in_s : float[NROWS][512]  (cp.async staged input slab)
#define OFF_HW2  8320
#define OFF_HF   8704
#define OFF_IN   8960

// ---------------------------------------------------------------------------
// Fused bicubic downsample, small-tile / many-pipelines variant.
// Block = 256 threads = one plane x 4 oh x full W (each thread: 4 rows).
// ~37.6 KB smem -> 6 blocks/SM: six independently-phased stage/compute
// pipelines per SM interleave their DRAM bursts (duty-cycle fix).
//   0) cp.async the NROWS x 512 slab into smem
//   1) Phase 1 (H): circular register window over the slab, FFMA2
//   2) Phase 2 (W): conflict-free LDS.64 gathers on packed row pairs
// Edge tiles (mirror folds) use a global-read generic path.
// ---------------------------------------------------------------------------
template<int TAPS>
__global__ __launch_bounds__(THREADS, 6) void resize_fused(
    const ull*   __restrict__ in,     // (BC, IN_HW, 256) column pairs
    const float* __restrict__ wh, const int* __restrict__ fh,   // H tables
    const float* __restrict__ ww, const int* __restrict__ fw,   // W tables
    float*       __restrict__ out)    // (BC, OUT_HW, OUT_HW)
{
    constexpr int NROWS  = 2 * TOH - 2 + TAPS;        // input rows per slab
    constexpr int CHUNKS = NROWS * (IN_HW * 4 / 16);  // 16B chunks per slab

    extern __shared__ char smem[];
    ull*   mid2 = (ull*)smem;                 // [TOH/2][MIDW]
    ull*   hw2  = (ull*)(smem + OFF_HW2);     // [TAPS][TOH]
    int*   hf_s = (int*)(smem + OFF_HF);      // [TAPS][TOH]
    float* in_s = (float*)(smem + OFF_IN);    // [NROWS][512]
    const ull* ins = (const ull*)in_s;        // [NROWS][256]

    const int tid   = threadIdx.x;            // 0..255 == col (2c, 2c+1)
    const int col   = tid;
    const int oh0   = blockIdx.x * TOH;
    const int plane = blockIdx.y;

    // ---- 0) Kick off the bulk async copy ASAP ----
    const int b0raw = fh[oh0];                        // uniform LDG broadcast
    int lo = b0raw < 0 ? 0 : b0raw;
    if (lo > IN_HW - NROWS) lo = IN_HW - NROWS;
    {
        const char* gsrc = (const char*)in
                         + ((size_t)plane * IN_HW * IN_HW
                          + (size_t)lo * IN_HW) * sizeof(float);
        char* sdst = (char*)in_s;
        #pragma unroll
        for (int k = 0; k < (CHUNKS + THREADS - 1) / THREADS; ++k) {
            const int i = tid + k * THREADS;
            if (i < CHUNKS) cp_async16(sdst + (size_t)i * 16, gsrc + (size_t)i * 16);
        }
        asm volatile("cp.async.commit_group;" ::: "memory");
    }

    // ---- Table loads overlap the bulk copy ----
    if (tid < TAPS * TOH) {
        const int t = tid / TOH, r = tid % TOH;
        const float w = wh[t * OUT_HW + oh0 + r];
        hw2 [t * TOH + r] = pack2(w, w);
        hf_s[t * TOH + r] = fh[t * OUT_HW + oh0 + r];
    }
    __syncthreads();

    // Fast iff H fov is linear: base + 2r + t (interior tiles => lo == b0raw).
    bool okp = true;
    if (tid < TAPS * TOH) {
        const int t = tid / TOH, r = tid % TOH;
        okp = (hf_s[t * TOH + r] == b0raw + 2 * r + t);
    }
    asm volatile("cp.async.wait_group 0;" ::: "memory");
    const int fast = __syncthreads_and(okp);    // barrier: all copies visible

    const ull* base = in + (size_t)plane * IN_HW * 256 + col;

    if (fast) {
        // ---- Phase 1 fast: circular register window over the smem slab ----
        // fast => lo == b0raw; slab row for (r, t) = 2r + t.
        const ull* sb = ins + col;
        ull v[TAPS];
        #pragma unroll
        for (int t = 0; t < TAPS; ++t)
            v[t] = sb[(size_t)t * 256];

        ull stash = 0;
        #pragma unroll
        for (int j = 0; j < RPH; ++j) {
            ull a0 = 0, a1 = 0;
            ffma2(a0, hw2[0 * TOH + j], v[(2 * j)     % TAPS]);
            ffma2(a1, hw2[1 * TOH + j], v[(2 * j + 1) % TAPS]);
            if (j < RPH - 1) {                // refill the two consumed slots
                v[(2 * j)     % TAPS] = sb[(size_t)(2 * j + TAPS)     * 256];
                v[(2 * j + 1) % TAPS] = sb[(size_t)(2 * j + TAPS + 1) * 256];
            }
            #pragma unroll
            for (int t = 2; t < TAPS; ++t) {
                if (t & 1) ffma2(a1, hw2[t * TOH + j], v[(2 * j + t) % TAPS]);
                else       ffma2(a0, hw2[t * TOH + j], v[(2 * j + t) % TAPS]);
            }
            const ull acc = fadd2(a0, a1);    // (evenColVal, oddColVal)
            if ((j & 1) == 0) stash = acc;
            else {                            // repack across the row pair
                float ex, ey, ox, oy;
                unpack2(stash, ex, ey);
                unpack2(acc,   ox, oy);
                const int rp = j >> 1;
                mid2[rp * MIDW + col]         = pack2(ex, ox);
                mid2[rp * MIDW + col + HALFP] = pack2(ey, oy);
            }
        }
    } else {
        // ---- Phase 1 generic (edge tiles with mirror folds): global reads ----
        float sx = 0.f, sy = 0.f;
        #pragma unroll
        for (int j = 0; j < RPH; ++j) {
            float ax = 0.f, ay = 0.f;
            #pragma unroll
            for (int t = 0; t < TAPS; ++t) {
                float w, wd; unpack2(hw2[t * TOH + j], w, wd);
                float x, y;  unpack2(base[(size_t)hf_s[t * TOH + j] * 256], x, y);
                ax = fmaf(w, x, ax);
                ay = fmaf(w, y, ay);
            }
            if ((j & 1) == 0) { sx = ax; sy = ay; }
            else {
                const int rp = j >> 1;
                mid2[rp * MIDW + col]         = pack2(sx, ax);
                mid2[rp * MIDW + col + HALFP] = pack2(sy, ay);
            }
        }
    }

    // Phase-2 per-thread tables AFTER phase 1 (short live range, no spills).
    ull pw[TAPS];
    int pr[TAPS];
    #pragma unroll
    for (int t = 0; t < TAPS; ++t) {
        const float w = ww[t * OUT_HW + col];
        pw[t] = pack2(w, w);
        pr[t] = pos_of(fw[t * OUT_HW + col]);
    }
    __syncthreads();

    // ---- Phase 2: W resize on packed row pairs ----
    float* ob = out + ((size_t)plane * OUT_HW + oh0) * OUT_HW + col;
    #pragma unroll
    for (int p = 0; p < RPH / 2; ++p) {
        ull a0 = 0, a1 = 0;
        #pragma unroll
        for (int t = 0; t < TAPS; ++t) {
            if (t & 1) ffma2(a1, pw[t], mid2[p * MIDW + pr[t]]);
            else       ffma2(a0, pw[t], mid2[p * MIDW + pr[t]]);
        }
        float x, y; unpack2(fadd2(a0, a1), x, y);
        ob[(size_t)(2 * p)     * OUT_HW] = x;   // row oh0+2p
        ob[(size_t)(2 * p + 1) * OUT_HW] = y;   // row oh0+2p+1
    }
}

// ---------------------------------------------------------------------------
// Generic-taps fallback (any taps; table path everywhere; static smem).
// ---------------------------------------------------------------------------
__global__ __launch_bounds__(THREADS) void resize_fused_generic(
    const ull*   __restrict__ in,
    const float* __restrict__ wh, const int* __restrict__ fh,
    const float* __restrict__ ww, const int* __restrict__ fw,
    float*       __restrict__ out, int taps)
{
    __shared__ ull   mid2[TOH / 2][MIDW];
    __shared__ float hw_s[MAX_T][TOH];
    __shared__ int   hf_s[MAX_T][TOH];

    const int tid   = threadIdx.x;
    const int col   = tid;
    const int oh0   = blockIdx.x * TOH;
    const int plane = blockIdx.y;

    if (tid < taps * TOH) {
        const int t = tid / TOH, r = tid % TOH;
        hw_s[t][r] = wh[t * OUT_HW + oh0 + r];
        hf_s[t][r] = fh[t * OUT_HW + oh0 + r];
    }
    float wr[MAX_T]; int pr[MAX_T];
    #pragma unroll
    for (int t = 0; t < MAX_T; ++t) {
        if (t < taps) {
            wr[t] = ww[t * OUT_HW + col];
            pr[t] = pos_of(fw[t * OUT_HW + col]);
        } else { wr[t] = 0.f; pr[t] = 0; }
    }
    __syncthreads();

    const ull* base = in + (size_t)plane * IN_HW * 256 + col;
    float sx = 0.f, sy = 0.f;
    for (int j = 0; j < RPH; ++j) {
        float ax = 0.f, ay = 0.f;
        #pragma unroll
        for (int t = 0; t < MAX_T; ++t) {
            if (t < taps) {
                float x, y; unpack2(base[(size_t)hf_s[t][j] * 256], x, y);
                ax = fmaf(hw_s[t][j], x, ax);
                ay = fmaf(hw_s[t][j], y, ay);
            }
        }
        if ((j & 1) == 0) { sx = ax; sy = ay; }
        else {
            const int rp = j >> 1;
            mid2[rp][col]         = pack2(sx, ax);
            mid2[rp][col + HALFP] = pack2(sy, ay);
        }
    }
    __syncthreads();

    float* ob = out + ((size_t)plane * OUT_HW + oh0) * OUT_HW + col;
    for (int p = 0; p < RPH / 2; ++p) {
        float ax = 0.f, ay = 0.f;
        #pragma unroll
        for (int t = 0; t < MAX_T; ++t) {
            if (t < taps) {
                float x, y; unpack2(mid2[p][pr[t]], x, y);
                ax = fmaf(wr[t], x, ax);
                ay = fmaf(wr[t], y, ay);
            }
        }
        ob[(size_t)(2 * p)     * OUT_HW] = ax;
        ob[(size_t)(2 * p + 1) * OUT_HW] = ay;
    }
}

// ---------------------------------------------------------------------------
// Inputs (metadata order): in_tensor, w2, fov2 (H axis), w3, fov3 (W axis)
// ---------------------------------------------------------------------------
#define LAUNCH_T(T)                                                            \
    do {                                                                       \
        constexpr int nrows = 2 * TOH - 2 + (T);                               \
        const int smemB = OFF_IN + nrows * IN_HW * 4;                          \
        cudaFuncSetAttribute(resize_fused<(T)>,                                \
            cudaFuncAttributeMaxDynamicSharedMemorySize, smemB);               \
        resize_fused<(T)><<<grid, THREADS, smemB>>>(in, w2, fov2, w3, fov3, out); \
    } while (0)

extern "C" void kernel_launch(void* const* d_in, const int* in_sizes, int n_in,
                              void* d_out, int out_size)
{
    const ull*   in   = (const ull*)  d_in[0];
    const float* w2   = (const float*)d_in[1];
    const int*   fov2 = (const int*)  d_in[2];
    const float* w3   = (const float*)d_in[3];
    const int*   fov3 = (const int*)  d_in[4];
    float* out = (float*)d_out;

    const int taps = in_sizes[1] / OUT_HW;
    dim3 grid(OUT_HW / TOH, BC);                  // (64, 96) = 6144 blocks

    switch (taps) {
    case 6:  LAUNCH_T(6);  break;
    case 7:  LAUNCH_T(7);  break;
    case 8:  LAUNCH_T(8);  break;
    case 9:  LAUNCH_T(9);  break;
    case 10: LAUNCH_T(10); break;
    case 11: LAUNCH_T(11); break;
    case 12: LAUNCH_T(12); break;
    default: resize_fused_generic<<<grid, THREADS>>>(in, w2, fov2, w3, fov3, out, taps); break;
    }
}